// round 7
// baseline (speedup 1.0000x reference)
#include <cuda_runtime.h>

// CosinLoss: loss = mean_i( 1 - dot(pc_i,aug_i)/(max(||pc_i||,eps)*max(||aug_i||,eps)) )
// N=16384 rows, D=1024 fp32. HBM streaming, 128 MiB read.
// K1: 4 rows per 256-thread CTA (64 thr/row, 4 float4/tensor/thread -> MLP_p1=8),
//     grid 4096, emits per-CTA sum of 4 row losses (no fences/atomics).
// K2: single 256-thread CTA reduces 4096 L2-resident partials -> mean.

#define CL_N   16384
#define CL_D   1024
#define CL_EPS 1e-12f
#define GRID1  4096

__device__ __align__(16) float g_part[GRID1];

// ---------------- Kernel 1: 4 rows/CTA cosine loss, per-CTA sum ----------------
__global__ __launch_bounds__(256)
void row_cos_kernel(const float* __restrict__ pc, const float* __restrict__ aug) {
    const int t    = threadIdx.x;
    const int wid  = t >> 5;        // 0..7; warps 2r,2r+1 own row r
    const int lane = t & 31;
    const int rsub = t >> 6;        // 0..3: row within CTA
    const int ct   = t & 63;        // thread index within row (64 thr/row)
    const size_t row = (size_t)blockIdx.x * 4 + rsub;

    const float4* __restrict__ p4 = reinterpret_cast<const float4*>(pc  + row * CL_D);
    const float4* __restrict__ a4 = reinterpret_cast<const float4*>(aug + row * CL_D);

    // 8 outstanding LDG.128 per thread, streaming hint.
    float4 p0 = __ldcs(&p4[ct      ]);
    float4 p1 = __ldcs(&p4[ct +  64]);
    float4 p2 = __ldcs(&p4[ct + 128]);
    float4 p3 = __ldcs(&p4[ct + 192]);
    float4 a0 = __ldcs(&a4[ct      ]);
    float4 a1 = __ldcs(&a4[ct +  64]);
    float4 a2 = __ldcs(&a4[ct + 128]);
    float4 a3 = __ldcs(&a4[ct + 192]);

    float dot = p0.x*a0.x + p0.y*a0.y + p0.z*a0.z + p0.w*a0.w
              + p1.x*a1.x + p1.y*a1.y + p1.z*a1.z + p1.w*a1.w
              + p2.x*a2.x + p2.y*a2.y + p2.z*a2.z + p2.w*a2.w
              + p3.x*a3.x + p3.y*a3.y + p3.z*a3.z + p3.w*a3.w;
    float npp = p0.x*p0.x + p0.y*p0.y + p0.z*p0.z + p0.w*p0.w
              + p1.x*p1.x + p1.y*p1.y + p1.z*p1.z + p1.w*p1.w
              + p2.x*p2.x + p2.y*p2.y + p2.z*p2.z + p2.w*p2.w
              + p3.x*p3.x + p3.y*p3.y + p3.z*p3.z + p3.w*p3.w;
    float naa = a0.x*a0.x + a0.y*a0.y + a0.z*a0.z + a0.w*a0.w
              + a1.x*a1.x + a1.y*a1.y + a1.z*a1.z + a1.w*a1.w
              + a2.x*a2.x + a2.y*a2.y + a2.z*a2.z + a2.w*a2.w
              + a3.x*a3.x + a3.y*a3.y + a3.z*a3.z + a3.w*a3.w;

    #pragma unroll
    for (int off = 16; off > 0; off >>= 1) {
        dot += __shfl_down_sync(0xFFFFFFFFu, dot, off);
        npp += __shfl_down_sync(0xFFFFFFFFu, npp, off);
        naa += __shfl_down_sync(0xFFFFFFFFu, naa, off);
    }

    __shared__ float s_dot[8], s_npp[8], s_naa[8];
    if (lane == 0) {
        s_dot[wid] = dot;
        s_npp[wid] = npp;
        s_naa[wid] = naa;
    }
    __syncthreads();

    // Warp 0, lanes 0..7: slot pairs (2r, 2r+1) belong to row r.
    if (wid == 0 && lane < 8) {
        dot = s_dot[lane];
        npp = s_npp[lane];
        naa = s_naa[lane];
        // combine the two warp-halves of each row
        dot += __shfl_xor_sync(0x000000FFu, dot, 1);
        npp += __shfl_xor_sync(0x000000FFu, npp, 1);
        naa += __shfl_xor_sync(0x000000FFu, naa, 1);

        float loss = 0.0f;
        if ((lane & 1) == 0) {
            float np_ = fmaxf(sqrtf(npp), CL_EPS);
            float na_ = fmaxf(sqrtf(naa), CL_EPS);
            loss = 1.0f - dot / (np_ * na_);
        }
        // sum the 4 row losses (held on even lanes) -> lane 0
        loss += __shfl_down_sync(0x000000FFu, loss, 4);
        loss += __shfl_down_sync(0x000000FFu, loss, 2);
        if (lane == 0)
            g_part[blockIdx.x] = loss;   // odd-lane contributions are 0
    }
}

// ---------------- Kernel 2: 4096 partials -> mean (256-thread single CTA) ----------------
__global__ __launch_bounds__(256)
void final_reduce_kernel(float* __restrict__ out) {
    const int t    = threadIdx.x;
    const int wid  = t >> 5;   // 0..7
    const int lane = t & 31;

    const float4* __restrict__ v4 = reinterpret_cast<const float4*>(g_part);
    // 4096 floats = 1024 float4; 256 threads x 4 float4 (L2-resident, MLP4).
    float4 v0 = v4[t      ];
    float4 v1 = v4[t + 256];
    float4 v2 = v4[t + 512];
    float4 v3 = v4[t + 768];
    float s = ((v0.x + v0.y) + (v0.z + v0.w))
            + ((v1.x + v1.y) + (v1.z + v1.w))
            + ((v2.x + v2.y) + (v2.z + v2.w))
            + ((v3.x + v3.y) + (v3.z + v3.w));

    #pragma unroll
    for (int off = 16; off > 0; off >>= 1)
        s += __shfl_down_sync(0xFFFFFFFFu, s, off);

    __shared__ float s_sum[8];
    if (lane == 0) s_sum[wid] = s;
    __syncthreads();

    if (wid == 0) {
        s = (lane < 8) ? s_sum[lane] : 0.0f;
        #pragma unroll
        for (int off = 4; off > 0; off >>= 1)
            s += __shfl_down_sync(0xFFFFFFFFu, s, off);
        if (lane == 0)
            out[0] = s * (1.0f / (float)CL_N);
    }
}

extern "C" void kernel_launch(void* const* d_in, const int* in_sizes, int n_in,
                              void* d_out, int out_size) {
    const float* pc  = (const float*)d_in[0];
    const float* aug = (const float*)d_in[1];
    float* out = (float*)d_out;

    row_cos_kernel<<<GRID1, 256>>>(pc, aug);
    final_reduce_kernel<<<1, 256>>>(out);
}

// round 8
// speedup vs baseline: 1.0452x; 1.0452x over previous
#include <cuda_runtime.h>

// CosinLoss fully fused, single kernel: loss = mean_i(1 - cos(pc_i, aug_i)).
// N=16384 rows, D=1024 fp32 (128 MiB streamed).
// 4 rows per 256-thread CTA (64 thr/row, 4 float4/tensor/thread -> MLP_p1=8), grid 4096.
// Epilogue: ONE packed u64 atomicAdd per CTA to a single accumulator:
//   bits [50..62] = CTA arrival count (1<<50 each), bits [0..49] = fixed-point sum
//   of (partial + 8.0) * 2^32  (bias keeps the value non-negative).
// Single-address atomics are totally ordered -> no fences. Integer adds -> exactly
// deterministic. Last CTA (old count == GRID-1) computes mean, writes out, resets to 0.

#define CL_N   16384
#define CL_D   1024
#define CL_EPS 1e-12f
#define GRID1  4096
#define CNT_SHIFT 50
#define SUM_MASK  ((1ULL << CNT_SHIFT) - 1ULL)
#define FP_SCALE  4294967296.0   // 2^32
#define BIAS      8.0

__device__ unsigned long long g_accum = 0ULL;

__global__ __launch_bounds__(256)
void cos_loss_fused(const float* __restrict__ pc, const float* __restrict__ aug,
                    float* __restrict__ out) {
    const int t    = threadIdx.x;
    const int wid  = t >> 5;        // 0..7; warps 2r,2r+1 own row r
    const int lane = t & 31;
    const int rsub = t >> 6;        // 0..3: row within CTA
    const int ct   = t & 63;        // thread index within row (64 thr/row)
    const size_t row = (size_t)blockIdx.x * 4 + rsub;

    const float4* __restrict__ p4 = reinterpret_cast<const float4*>(pc  + row * CL_D);
    const float4* __restrict__ a4 = reinterpret_cast<const float4*>(aug + row * CL_D);

    // 8 outstanding LDG.128 per thread, streaming hint.
    float4 p0 = __ldcs(&p4[ct      ]);
    float4 p1 = __ldcs(&p4[ct +  64]);
    float4 p2 = __ldcs(&p4[ct + 128]);
    float4 p3 = __ldcs(&p4[ct + 192]);
    float4 a0 = __ldcs(&a4[ct      ]);
    float4 a1 = __ldcs(&a4[ct +  64]);
    float4 a2 = __ldcs(&a4[ct + 128]);
    float4 a3 = __ldcs(&a4[ct + 192]);

    float dot = p0.x*a0.x + p0.y*a0.y + p0.z*a0.z + p0.w*a0.w
              + p1.x*a1.x + p1.y*a1.y + p1.z*a1.z + p1.w*a1.w
              + p2.x*a2.x + p2.y*a2.y + p2.z*a2.z + p2.w*a2.w
              + p3.x*a3.x + p3.y*a3.y + p3.z*a3.z + p3.w*a3.w;
    float npp = p0.x*p0.x + p0.y*p0.y + p0.z*p0.z + p0.w*p0.w
              + p1.x*p1.x + p1.y*p1.y + p1.z*p1.z + p1.w*p1.w
              + p2.x*p2.x + p2.y*p2.y + p2.z*p2.z + p2.w*p2.w
              + p3.x*p3.x + p3.y*p3.y + p3.z*p3.z + p3.w*p3.w;
    float naa = a0.x*a0.x + a0.y*a0.y + a0.z*a0.z + a0.w*a0.w
              + a1.x*a1.x + a1.y*a1.y + a1.z*a1.z + a1.w*a1.w
              + a2.x*a2.x + a2.y*a2.y + a2.z*a2.z + a2.w*a2.w
              + a3.x*a3.x + a3.y*a3.y + a3.z*a3.z + a3.w*a3.w;

    #pragma unroll
    for (int off = 16; off > 0; off >>= 1) {
        dot += __shfl_down_sync(0xFFFFFFFFu, dot, off);
        npp += __shfl_down_sync(0xFFFFFFFFu, npp, off);
        naa += __shfl_down_sync(0xFFFFFFFFu, naa, off);
    }

    __shared__ float s_dot[8], s_npp[8], s_naa[8];
    if (lane == 0) {
        s_dot[wid] = dot;
        s_npp[wid] = npp;
        s_naa[wid] = naa;
    }
    __syncthreads();

    // Warp 0, lanes 0..7: slot pairs (2r, 2r+1) belong to row r.
    if (wid == 0 && lane < 8) {
        dot = s_dot[lane];
        npp = s_npp[lane];
        naa = s_naa[lane];
        dot += __shfl_xor_sync(0x000000FFu, dot, 1);
        npp += __shfl_xor_sync(0x000000FFu, npp, 1);
        naa += __shfl_xor_sync(0x000000FFu, naa, 1);

        float loss = 0.0f;
        if ((lane & 1) == 0) {
            float np_ = fmaxf(sqrtf(npp), CL_EPS);
            float na_ = fmaxf(sqrtf(naa), CL_EPS);
            loss = 1.0f - dot / (np_ * na_);
        }
        loss += __shfl_down_sync(0x000000FFu, loss, 4);
        loss += __shfl_down_sync(0x000000FFu, loss, 2);

        if (lane == 0) {
            // Fixed-point encode the CTA partial (4 rows, value in (-8, 16) with bias -> (0, 24)).
            // Sum over 4096 CTAs < 24 * 4096 * 2^32 < 2^49 < 2^50 -> no carry into count.
            unsigned long long fp =
                (unsigned long long)((double)loss * FP_SCALE + BIAS * FP_SCALE + 0.5);
            unsigned long long word = (1ULL << CNT_SHIFT) | fp;
            unsigned long long old  = atomicAdd(&g_accum, word);

            if ((old >> CNT_SHIFT) == (GRID1 - 1)) {
                // We are the last CTA: old + our word is the grand total.
                unsigned long long total = (old + word) & SUM_MASK;
                double sum = (double)total * (1.0 / FP_SCALE) - BIAS * (double)GRID1;
                out[0] = (float)(sum * (1.0 / (double)CL_N));
                atomicExch(&g_accum, 0ULL);   // reset for next graph replay
            }
        }
    }
}

extern "C" void kernel_launch(void* const* d_in, const int* in_sizes, int n_in,
                              void* d_out, int out_size) {
    const float* pc  = (const float*)d_in[0];
    const float* aug = (const float*)d_in[1];
    float* out = (float*)d_out;

    cos_loss_fused<<<GRID1, 256>>>(pc, aug, out);
}